// round 1
// baseline (speedup 1.0000x reference)
#include <cuda_runtime.h>
#include <math.h>

// Problem constants
#define BB   128
#define LLEN 52
#define TT   51      // decode steps
#define EE   512
#define DD   512
#define VV   10000
#define FEATN 2048
#define NPP  196
#define G4   2048    // 4*D
#define MROWS (BB*TT)        // 6528

// ---------------- scratch (static device globals; no allocation) ----------------
__device__ float g_X[(size_t)MROWS * G4];      // 53.5 MB: precomputed x_t@w_ih.T + b_ih + b_hh
__device__ float g_H[(size_t)MROWS * DD];      // 13.4 MB: h_new history
__device__ float g_feats[(size_t)BB * FEATN];  // 1 MB: sorted mean features
__device__ float g_hbuf[2][BB * DD];           // ping-pong h
__device__ float g_c[BB * DD];
__device__ int   g_sort[BB];
__device__ int   g_declen[BB];
__device__ int   g_capsS[BB * LLEN];
__device__ int   g_rowmap[MROWS];

// ---------------- kernel: sort + gathers + tail outputs + zero c ----------------
__global__ void k_sort(const int* __restrict__ caplen, const int* __restrict__ caps,
                       float* __restrict__ out, long long out_size) {
    __shared__ int lens[BB];
    int b = threadIdx.x;
    lens[b] = caplen[b];              // caption_lengths is (B,1)
    __syncthreads();
    int my = lens[b];
    int rank = 0;
    for (int j = 0; j < BB; j++) {
        int lj = lens[j];
        if (lj > my || (lj == my && j < b)) rank++;   // stable descending
    }
    g_sort[rank] = b;
    __syncthreads();                  // single block: global writes visible after sync
    int s = g_sort[b];
    int dl = lens[s] - 1;
    g_declen[b] = dl;
    for (int l = 0; l < LLEN; l++) g_capsS[b * LLEN + l] = caps[s * LLEN + l];
    for (int t = 0; t < TT; t++)   g_rowmap[b * TT + t] = g_capsS[b * LLEN + t];
    // zero c
    for (int d = 0; d < DD; d++) g_c[b * DD + d] = 0.0f;
    // tail outputs: caps (float), dec_len, sort_ind
    long long off = (long long)MROWS * VV;
    if (out_size >= off + (long long)BB * LLEN + 2 * BB) {
        for (int l = 0; l < LLEN; l++) out[off + b * LLEN + l] = (float)g_capsS[b * LLEN + l];
        out[off + (long long)BB * LLEN + b]      = (float)dl;
        out[off + (long long)BB * LLEN + BB + b] = (float)s;
    }
}

// ---------------- kernel: mean over NP, gathered by sort_ind ----------------
__global__ __launch_bounds__(256) void k_mean(const float* __restrict__ img) {
    int p = blockIdx.x;               // sorted row
    int s = g_sort[p];
    const float* base = img + (long long)s * NPP * FEATN;
    int f0 = threadIdx.x;             // 256 threads, 8 features each
    float acc[8] = {0,0,0,0,0,0,0,0};
    for (int q = 0; q < NPP; q++) {
        const float* rowp = base + (long long)q * FEATN;
        #pragma unroll
        for (int u = 0; u < 8; u++) acc[u] += rowp[f0 + u * 256];
    }
    #pragma unroll
    for (int u = 0; u < 8; u++)
        g_feats[(long long)p * FEATN + f0 + u * 256] = acc[u] * (1.0f / 196.0f);
}

// ---------------- generic tiled NT GEMM: C = A @ B^T (+bias) ----------------
// A: M x K row-major (lda), optionally row-indirected via rowmap
// B: N x K row-major (ldb)  (i.e. we compute against B transposed)
// MODE 0: C = acc + bias1 (+ bias2)        (used for X precompute, h0)
// MODE 2: C = mask(row) ? acc + bias1 : 0  (word logits with mask)
template<int BM, int BN, int BK, int TM, int TN, int MODE>
__global__ __launch_bounds__((BM/TM)*(BN/TN)) void gemm_nt(
    const float* __restrict__ A, int lda,
    const float* __restrict__ B, int ldb,
    const float* __restrict__ bias1, const float* __restrict__ bias2,
    float* __restrict__ C, int ldc,
    int M, int N, int K,
    const int* __restrict__ rowmap,
    const int* __restrict__ declen)
{
    constexpr int NT = (BM / TM) * (BN / TN);
    __shared__ float As[BK][BM + 4];
    __shared__ float Bs[BK][BN + 4];
    const int tid = threadIdx.x;
    const int tx = tid % (BN / TN);
    const int ty = tid / (BN / TN);
    const int row0 = blockIdx.y * BM;
    const int col0 = blockIdx.x * BN;

    float acc[TM][TN];
    #pragma unroll
    for (int i = 0; i < TM; i++)
        #pragma unroll
        for (int j = 0; j < TN; j++) acc[i][j] = 0.0f;

    for (int k0 = 0; k0 < K; k0 += BK) {
        #pragma unroll 2
        for (int e = tid; e < BM * BK; e += NT) {
            int r = e / BK, k = e % BK;
            int gr = row0 + r;                       // M is multiple of BM for all uses
            int ar = rowmap ? rowmap[gr] : gr;
            As[k][r] = A[(long long)ar * lda + k0 + k];
        }
        #pragma unroll 2
        for (int e = tid; e < BN * BK; e += NT) {
            int c = e / BK, k = e % BK;
            int gc = col0 + c;
            Bs[k][c] = (gc < N) ? B[(long long)gc * ldb + k0 + k] : 0.0f;
        }
        __syncthreads();
        #pragma unroll
        for (int kk = 0; kk < BK; kk++) {
            float ra[TM], rb[TN];
            #pragma unroll
            for (int i = 0; i < TM; i += 4) {
                float4 v = *reinterpret_cast<const float4*>(&As[kk][ty * TM + i]);
                ra[i] = v.x; ra[i+1] = v.y; ra[i+2] = v.z; ra[i+3] = v.w;
            }
            #pragma unroll
            for (int j = 0; j < TN; j += 4) {
                float4 v = *reinterpret_cast<const float4*>(&Bs[kk][tx * TN + j]);
                rb[j] = v.x; rb[j+1] = v.y; rb[j+2] = v.z; rb[j+3] = v.w;
            }
            #pragma unroll
            for (int i = 0; i < TM; i++)
                #pragma unroll
                for (int j = 0; j < TN; j++)
                    acc[i][j] += ra[i] * rb[j];
        }
        __syncthreads();
    }

    const bool has_b2 = (bias2 != nullptr);
    #pragma unroll
    for (int i = 0; i < TM; i++) {
        int gr = row0 + ty * TM + i;
        float mval = 1.0f;
        if (MODE == 2) {
            int b = gr / TT, t = gr - b * TT;
            mval = (t < declen[b]) ? 1.0f : 0.0f;
        }
        #pragma unroll
        for (int j = 0; j < TN; j++) {
            int gc = col0 + tx * TN + j;
            if (gc < N) {
                float v = acc[i][j] + bias1[gc] + (has_b2 ? bias2[gc] : 0.0f);
                if (MODE == 2) v *= mval;
                C[(long long)gr * ldc + gc] = v;
            }
        }
    }
}

// ---------------- kernel: one LSTM step (gates GEMM + pointwise, fused) ----------------
// grid: (32 d-tiles of 16, 4 b-tiles of 32), 256 threads.
// Each block computes gate columns {d, d+512, d+1024, d+1536} for its d-range,
// so the pointwise update (and c state) stays block-local. h ping-pongs.
__global__ __launch_bounds__(256) void k_step(const float* __restrict__ w_hh, int t) {
    __shared__ float As[16][36];
    __shared__ float Bs[16][68];
    __shared__ float Gs[32][68];
    const int tid = threadIdx.x;
    const int d0 = blockIdx.x * 16;
    const int b0 = blockIdx.y * 32;
    const float* hin  = g_hbuf[t & 1];
    float*       hout = g_hbuf[(t + 1) & 1];
    const int tx = tid & 15, ty = tid >> 4;   // 16x16 threads; each 2 rows x 4 cols
    float acc[2][4] = {{0,0,0,0},{0,0,0,0}};

    for (int k0 = 0; k0 < DD; k0 += 16) {
        #pragma unroll
        for (int e = tid; e < 512; e += 256) {
            int r = e >> 4, k = e & 15;
            As[k][r] = hin[(b0 + r) * DD + k0 + k];
        }
        #pragma unroll
        for (int e = tid; e < 1024; e += 256) {
            int c = e >> 4, k = e & 15;
            int j = ((c >> 4) << 9) + d0 + (c & 15);   // quadrant*512 + d
            Bs[k][c] = w_hh[(long long)j * DD + k0 + k];
        }
        __syncthreads();
        #pragma unroll
        for (int kk = 0; kk < 16; kk++) {
            float a0 = As[kk][ty * 2], a1 = As[kk][ty * 2 + 1];
            float4 bv = *reinterpret_cast<const float4*>(&Bs[kk][tx * 4]);
            acc[0][0] += a0 * bv.x; acc[0][1] += a0 * bv.y;
            acc[0][2] += a0 * bv.z; acc[0][3] += a0 * bv.w;
            acc[1][0] += a1 * bv.x; acc[1][1] += a1 * bv.y;
            acc[1][2] += a1 * bv.z; acc[1][3] += a1 * bv.w;
        }
        __syncthreads();
    }
    // add precomputed input-side gates, stage in smem for the pointwise reshuffle
    #pragma unroll
    for (int i = 0; i < 2; i++) {
        int rl = ty * 2 + i;
        int b = b0 + rl;
        const float* xrow = g_X + (long long)(b * TT + t) * G4;
        #pragma unroll
        for (int jj = 0; jj < 4; jj++) {
            int c = tx * 4 + jj;
            int jg = ((c >> 4) << 9) + d0 + (c & 15);
            Gs[rl][c] = acc[i][jj] + xrow[jg];
        }
    }
    __syncthreads();
    // pointwise LSTM update: 32 b x 16 d = 512 elems
    #pragma unroll
    for (int e = tid; e < 512; e += 256) {
        int rl = e >> 4, dd = e & 15;
        int b = b0 + rl, d = d0 + dd;
        float gi = Gs[rl][dd];
        float gf = Gs[rl][16 + dd];
        float gg = Gs[rl][32 + dd];
        float go = Gs[rl][48 + dd];
        float si = 1.0f / (1.0f + expf(-gi));
        float sf = 1.0f / (1.0f + expf(-gf));
        float tg = tanhf(gg);
        float so = 1.0f / (1.0f + expf(-go));
        float cold = g_c[b * DD + d];
        float cnew = sf * cold + si * tg;
        float hnew = so * tanhf(cnew);
        g_H[(long long)(b * TT + t) * DD + d] = hnew;   // pred uses h_new (mask applied later)
        bool m = t < g_declen[b];
        hout[b * DD + d] = m ? hnew : hin[b * DD + d];
        if (m) g_c[b * DD + d] = cnew;
    }
}

// ---------------- launch ----------------
extern "C" void kernel_launch(void* const* d_in, const int* in_sizes, int n_in,
                              void* d_out, int out_size) {
    const float* img    = (const float*)d_in[0];
    const int*   caps   = (const int*)  d_in[1];
    const int*   caplen = (const int*)  d_in[2];
    const float* embtab = (const float*)d_in[3];
    const float* att1_w = (const float*)d_in[4];
    const float* att1_b = (const float*)d_in[5];
    const float* w_ih   = (const float*)d_in[6];
    const float* w_hh   = (const float*)d_in[7];
    const float* b_ih   = (const float*)d_in[8];
    const float* b_hh   = (const float*)d_in[9];
    const float* word_w = (const float*)d_in[10];
    const float* word_b = (const float*)d_in[11];
    float* out = (float*)d_out;

    float *pX, *pH, *pFeats, *pHbuf;
    int *pRowmap, *pDeclen;
    cudaGetSymbolAddress((void**)&pX,     g_X);
    cudaGetSymbolAddress((void**)&pH,     g_H);
    cudaGetSymbolAddress((void**)&pFeats, g_feats);
    cudaGetSymbolAddress((void**)&pHbuf,  g_hbuf);
    cudaGetSymbolAddress((void**)&pRowmap,g_rowmap);
    cudaGetSymbolAddress((void**)&pDeclen,g_declen);

    // 1) sort / gather / tail outputs / zero c
    k_sort<<<1, BB>>>(caplen, caps, out, (long long)out_size);

    // 2) sorted mean features
    k_mean<<<BB, 256>>>(img);

    // 3) h0 = feats_mean_s @ att1_w^T + att1_b   (128 x 512, K=2048) -> hbuf[0]
    {
        dim3 grid(DD / 64, BB / 64);
        gemm_nt<64, 64, 16, 4, 4, 0><<<grid, 256>>>(
            pFeats, FEATN, att1_w, FEATN, att1_b, nullptr,
            pHbuf, DD, BB, DD, FEATN, nullptr, nullptr);
    }

    // 4) X = emb[tokens] @ w_ih^T + b_ih + b_hh   (6528 x 2048, K=512)
    {
        dim3 grid(G4 / 128, MROWS / 128);
        gemm_nt<128, 128, 16, 8, 8, 0><<<grid, 256>>>(
            embtab, EE, w_ih, EE, b_ih, b_hh,
            pX, G4, MROWS, G4, EE, pRowmap, nullptr);
    }

    // 5) LSTM recurrence: 51 fused step kernels
    {
        dim3 grid(DD / 16, BB / 32);
        for (int t = 0; t < TT; t++)
            k_step<<<grid, 256>>>(w_hh, t);
    }

    // 6) predictions = mask * (H @ word_w^T + word_b)   (6528 x 10000, K=512)
    {
        dim3 grid((VV + 127) / 128, MROWS / 128);
        gemm_nt<128, 128, 16, 8, 8, 2><<<grid, 256>>>(
            pH, DD, word_w, DD, word_b, nullptr,
            out, VV, MROWS, VV, DD, nullptr, pDeclen);
    }
}